// round 15
// baseline (speedup 1.0000x reference)
#include <cuda_runtime.h>

// GrassmannNN: SITE=8, DIM=16, D=32, B=8192.
// TWO kernels, both wide, no inter-block sync anywhere:
//   A : 225 blocks — build 28 16x16 layer matrices M + tanh(head) vectors
//   BC: 256 blocks — each block loads M (28KB, L2-warm) into smem and
//       forwards its own 32 rows' patterns directly (8 warps x 4 ILP slots),
//       staging + coalesced float4 store. No pattern table, no kernel B.

__device__ float g_M[7 * 2 * 2 * 256];          // [l][bit][s][i][k], sign folded
__device__ float g_h[32];                       // tanh(head) per bit

// ---------------------------------------------------------------------------
// Kernel A (unchanged, proven): blocks 0..223 -> one (l, ig) slab each,
// block 224 -> head vectors.
// ---------------------------------------------------------------------------
__global__ void __launch_bounds__(256)
precompute_kernel(const float* __restrict__ emb,
                  const float* __restrict__ head_w,
                  const float* __restrict__ body_w) {
    __shared__ __align__(16) float sh[1024];
    const int b = blockIdx.x;
    const int t = threadIdx.x;

    if (b < 224) {
        const int l = b >> 5, ig = b & 31;
        reinterpret_cast<float4*>(sh)[t] =
            reinterpret_cast<const float4*>(body_w + (size_t)(l * 32 + ig) * 1024)[t];
        __syncthreads();
        if (t < 32) {
            const int bit = t >> 4, k = t & 15;
            const int s1 = ig >> 4, i = ig & 15;
            const int s = bit ? (1 - s1) : s1;
            const float* e = emb + ((l + 1) * 2 + bit) * 16;
            float acc = 0.f;
#pragma unroll
            for (int j = 0; j < 16; ++j)
                acc = fmaf(e[j], sh[(bit * 16 + j) * 32 + s * 16 + k], acc);
            if (bit == 1 && s == 0) acc = -acc;
            g_M[(((l * 2 + bit) * 2 + s) * 16 + i) * 16 + k] = acc;
        }
    } else if (t < 32) {
        const int bit = t >> 4, j = t & 15;
        const float* e = emb + bit * 16;                 // embedding[0][bit]
        float acc = 0.f;
#pragma unroll
        for (int k = 0; k < 16; ++k)
            acc = fmaf(e[k], head_w[(bit * 16 + k) * 32 + bit * 16 + j], acc);
        g_h[bit * 16 + j] = tanhf(acc);
    }
    cudaTriggerProgrammaticLaunchCompletion();
}

// ---------------------------------------------------------------------------
// Kernel BC: 256 blocks x 256 thr; block handles rows 32b..32b+31.
// Warp w owns rows 4w..4w+3 as 4 ILP slots. M in smem with 272-float
// sector stride (s=0/s=1 lane halves hit disjoint banks).
// ---------------------------------------------------------------------------
#define MS 272   // padded sector stride (floats); 272 % 32 == 16

__global__ void __launch_bounds__(256)
forward_gather_kernel(const int* __restrict__ data, float4* __restrict__ out) {
    __shared__ __align__(16) float shM[28 * MS];
    __shared__ __align__(16) float shO[32 * 64];
    __shared__ float shh[32];
    __shared__ int shP[32];
    const int b = blockIdx.x;
    const int t = threadIdx.x;

    // ---- prolog (input-only; overlaps kernel A via PDL) ----
    if (t < 32) {
        const int4* d4 = reinterpret_cast<const int4*>(data + (b * 32 + t) * 8);
        const int4 a = __ldg(d4);
        const int4 c = __ldg(d4 + 1);
        shP[t] = a.x | (a.y << 1) | (a.z << 2) | (a.w << 3)
               | (c.x << 4) | (c.y << 5) | (c.z << 6) | (c.w << 7);
    }

    cudaGridDependencySynchronize();            // wait for A's g_M / g_h

    // ---- M -> padded smem (28 sectors of 256 floats -> stride 272) ----
    {
        const float4* gM4 = reinterpret_cast<const float4*>(g_M);
        float4* sM4 = reinterpret_cast<float4*>(shM);
#pragma unroll
        for (int j = 0; j < 7; ++j) {
            const int f = t + j * 256;          // 0..1791
            const int sec = f >> 6;             // 64 float4 per sector
            const int r = f & 63;
            sM4[sec * (MS / 4) + r] = gM4[f];
        }
    }
    if (t < 32) shh[t] = g_h[t];
    __syncthreads();

    // ---- forward: 4 rows per warp ----
    const int w = t >> 5, lane = t & 31;
    const int s = lane >> 4, k = lane & 15;
    const int p0 = shP[w * 4 + 0];
    const int p1 = shP[w * 4 + 1];
    const int p2 = shP[w * 4 + 2];
    const int p3 = shP[w * 4 + 3];

    float u0 = (s == (p0 & 1)) ? shh[(p0 & 1) * 16 + k] : 0.f;
    float u1 = (s == (p1 & 1)) ? shh[(p1 & 1) * 16 + k] : 0.f;
    float u2 = (s == (p2 & 1)) ? shh[(p2 & 1) * 16 + k] : 0.f;
    float u3 = (s == (p3 & 1)) ? shh[(p3 & 1) * 16 + k] : 0.f;

#pragma unroll
    for (int l = 0; l < 7; ++l) {
        const int b0 = (p0 >> (l + 1)) & 1;
        const int b1 = (p1 >> (l + 1)) & 1;
        const int b2 = (p2 >> (l + 1)) & 1;
        const int b3 = (p3 >> (l + 1)) & 1;
        const int o0 = ((l * 2 + b0) * 2 + s) * MS + k;
        const int o1 = ((l * 2 + b1) * 2 + s) * MS + k;
        const int o2 = ((l * 2 + b2) * 2 + s) * MS + k;
        const int o3 = ((l * 2 + b3) * 2 + s) * MS + k;
        const int c0 = (b0 ? (1 - s) : s) << 4;
        const int c1 = (b1 ? (1 - s) : s) << 4;
        const int c2 = (b2 ? (1 - s) : s) << 4;
        const int c3 = (b3 ? (1 - s) : s) << 4;
        float a0 = 0.f, a1 = 0.f, a2 = 0.f, a3 = 0.f;
#pragma unroll
        for (int i = 0; i < 16; ++i) {
            a0 = fmaf(__shfl_sync(0xffffffffu, u0, c0 + i), shM[o0 + i * 16], a0);
            a1 = fmaf(__shfl_sync(0xffffffffu, u1, c1 + i), shM[o1 + i * 16], a1);
            a2 = fmaf(__shfl_sync(0xffffffffu, u2, c2 + i), shM[o2 + i * 16], a2);
            a3 = fmaf(__shfl_sync(0xffffffffu, u3, c3 + i), shM[o3 + i * 16], a3);
        }
        u0 = tanhf(a0); u1 = tanhf(a1); u2 = tanhf(a2); u3 = tanhf(a3);
    }

    // ---- stage this warp's 4 rows (live + structural zeros) ----
    {
        const int r0 = w * 4;
        const int live = 48 * s + k;            // s*32 + s*16 + k
        const int zero = 16 + 16 * s + k;       // s*32 + (1-s)*16 + k
        shO[(r0 + 0) * 64 + live] = u0;  shO[(r0 + 0) * 64 + zero] = 0.f;
        shO[(r0 + 1) * 64 + live] = u1;  shO[(r0 + 1) * 64 + zero] = 0.f;
        shO[(r0 + 2) * 64 + live] = u2;  shO[(r0 + 2) * 64 + zero] = 0.f;
        shO[(r0 + 3) * 64 + live] = u3;  shO[(r0 + 3) * 64 + zero] = 0.f;
    }
    __syncthreads();

    // ---- coalesced store: 32 rows x 64 floats = 512 float4 ----
    {
        const float4* s4 = reinterpret_cast<const float4*>(shO);
        float4* o4 = out + (size_t)b * 512;
        o4[t] = s4[t];
        o4[t + 256] = s4[t + 256];
    }
}

extern "C" void kernel_launch(void* const* d_in, const int* in_sizes, int n_in,
                              void* d_out, int out_size) {
    const int*   data      = (const int*)d_in[0];    // (8192, 8) int32
    const float* embedding = (const float*)d_in[1];  // (8, 2, 16)
    const float* head_w    = (const float*)d_in[2];  // (32, 32)
    const float* body_w    = (const float*)d_in[3];  // (7, 32, 32, 32)

    precompute_kernel<<<225, 256>>>(embedding, head_w, body_w);

    cudaLaunchAttribute attr[1];
    attr[0].id = cudaLaunchAttributeProgrammaticStreamSerialization;
    attr[0].val.programmaticStreamSerializationAllowed = 1;

    cudaLaunchConfig_t cfg = {};
    cfg.gridDim = dim3(256);
    cfg.blockDim = dim3(256);
    cfg.stream = 0;
    cfg.attrs = attr;
    cfg.numAttrs = 1;
    cudaLaunchKernelEx(&cfg, forward_gather_kernel, data, (float4*)d_out);
}